// round 6
// baseline (speedup 1.0000x reference)
#include <cuda_runtime.h>
#include <cuda_bf16.h>
#include <math.h>
#include <stdint.h>

#define Hdim 128
#define Wdim 128
#define Cdim 128
#define NPIX (Hdim * Wdim)
#define HEADS 4
#define HD 32
#define KW 7
#define KK 49
#define RPBW 13
#define QSCALE 0.17677669529663689f

// ---------------- scratch ----------------
__device__ float g_q  [NPIX * Cdim];              // q fp32 (scaled)
__device__ float g_x2 [NPIX * Cdim];              // x + proj(attn)
__device__ __nv_bfloat16 g_vb [NPIX * Cdim];      // v bf16
__device__ __nv_bfloat16 g_kb [NPIX * Cdim];      // k bf16
__device__ __nv_bfloat16 s_xn_hi[NPIX * Cdim];
__device__ __nv_bfloat16 s_xn_lo[NPIX * Cdim];
__device__ __nv_bfloat16 s_y_hi [NPIX * Cdim];
__device__ __nv_bfloat16 s_y_lo [NPIX * Cdim];
__device__ __nv_bfloat16 s_att_hi[NPIX * Cdim];
__device__ __nv_bfloat16 s_att_lo[NPIX * Cdim];
__device__ __nv_bfloat16 s_h_hi [NPIX * 512];
__device__ __nv_bfloat16 s_h_lo [NPIX * 512];
// weights: qv@0 (32768), k@32768, proj@49152, fc1@65536, fc2@131072
__device__ __nv_bfloat16 s_w_hi[196608];
__device__ __nv_bfloat16 s_w_lo[196608];

// ---------------- helpers ----------------
__device__ __forceinline__ uint32_t smem_u32(const void* p) {
    uint32_t a;
    asm("{ .reg .u64 t; cvta.to.shared.u64 t, %1; cvt.u32.u64 %0, t; }" : "=r"(a) : "l"(p));
    return a;
}
__device__ __forceinline__ void ldm_x4(uint32_t& r0, uint32_t& r1, uint32_t& r2, uint32_t& r3,
                                       uint32_t addr) {
    asm volatile("ldmatrix.sync.aligned.m8n8.x4.shared.b16 {%0,%1,%2,%3}, [%4];"
        : "=r"(r0), "=r"(r1), "=r"(r2), "=r"(r3) : "r"(addr));
}
__device__ __forceinline__ void mma_bf16(float* d, const uint32_t* a, const uint32_t* b) {
    asm volatile("mma.sync.aligned.m16n8k16.row.col.f32.bf16.bf16.f32 "
        "{%0,%1,%2,%3}, {%4,%5,%6,%7}, {%8,%9}, {%0,%1,%2,%3};"
        : "+f"(d[0]), "+f"(d[1]), "+f"(d[2]), "+f"(d[3])
        : "r"(a[0]), "r"(a[1]), "r"(a[2]), "r"(a[3]), "r"(b[0]), "r"(b[1]));
}
__device__ __forceinline__ void cp16(uint32_t dst, const void* src) {
    asm volatile("cp.async.ca.shared.global [%0], [%1], 16;" :: "r"(dst), "l"(src));
}
#define CP_COMMIT() asm volatile("cp.async.commit_group;" ::: "memory")
#define CP_WAIT(n)  asm volatile("cp.async.wait_group %0;" :: "n"(n) : "memory")
__device__ __forceinline__ void splitf(float a, __nv_bfloat16& h, __nv_bfloat16& l) {
    h = __float2bfloat16(a);
    l = __float2bfloat16(a - __bfloat162float(h));
}

// ---------------- prep: LN1 + split_y + split_w, one launch ----------------
__global__ void prep_kernel(const float* __restrict__ x,
                            const float* __restrict__ n1w, const float* __restrict__ n1b,
                            const float* __restrict__ y,
                            const float* __restrict__ qvw, const float* __restrict__ kw,
                            const float* __restrict__ pw,  const float* __restrict__ f1,
                            const float* __restrict__ f2,
                            __nv_bfloat16* __restrict__ xnh, __nv_bfloat16* __restrict__ xnl,
                            __nv_bfloat16* __restrict__ yh,  __nv_bfloat16* __restrict__ yl,
                            __nv_bfloat16* __restrict__ wh,  __nv_bfloat16* __restrict__ wl)
{
    const int b = blockIdx.x, tid = threadIdx.x;
    if (b < 8192) {
        // LN1: 2 rows per block (128 threads each)
        const int row = b * 2 + (tid >> 7);
        const int r = tid & 127;
        float v = x[row * Cdim + r];
        float s = v, s2 = v * v;
        #pragma unroll
        for (int o = 16; o; o >>= 1) {
            s  += __shfl_xor_sync(0xffffffffu, s,  o);
            s2 += __shfl_xor_sync(0xffffffffu, s2, o);
        }
        __shared__ float ss[8], ss2[8];
        const int wrp = tid >> 5;
        if ((tid & 31) == 0) { ss[wrp] = s; ss2[wrp] = s2; }
        __syncthreads();
        const int base = (tid >> 7) * 4;
        s  = ss[base]  + ss[base + 1]  + ss[base + 2]  + ss[base + 3];
        s2 = ss2[base] + ss2[base + 1] + ss2[base + 2] + ss2[base + 3];
        float mu  = s * (1.0f / Cdim);
        float var = s2 * (1.0f / Cdim) - mu * mu;
        float rr = (v - mu) * rsqrtf(var + 1e-5f) * n1w[r] + n1b[r];
        splitf(rr, xnh[row * Cdim + r], xnl[row * Cdim + r]);
    } else if (b < 12288) {
        const int i = (b - 8192) * 512 + tid * 2;
        splitf(y[i],     yh[i],     yl[i]);
        splitf(y[i + 1], yh[i + 1], yl[i + 1]);
    } else {
        const int wi = (b - 12288) * 512 + tid * 2;
        #pragma unroll
        for (int e = 0; e < 2; e++) {
            int q = wi + e;
            if (q < 196608) {
                float v;
                if      (q < 32768)  v = qvw[q];
                else if (q < 49152)  v = kw [q - 32768];
                else if (q < 65536)  v = pw [q - 49152];
                else if (q < 131072) v = f1 [q - 65536];
                else                 v = f2 [q - 131072];
                splitf(v, wh[q], wl[q]);
            }
        }
    }
}

// ---------------- shared GEMM core: 64x128 tile, cp.async 2-stage ----------
#define PITCH 72
#define OFF_AL 9216
#define OFF_WH 18432
#define STAGE  55296
#define GSMEM  (2 * STAGE)

template <int KTOT>
__device__ __forceinline__ void gemm_core(
    const __nv_bfloat16* __restrict__ Ahi, const __nv_bfloat16* __restrict__ Alo,
    const __nv_bfloat16* __restrict__ Whi, const __nv_bfloat16* __restrict__ Wlo,
    int bm, int bn, uint32_t sb, float acc[8][4])
{
    const int tid = threadIdx.x, lane = tid & 31, wid = tid >> 5;
    const int wm = wid & 3, wn = wid >> 2;
    const int nch = KTOT / 64;

    #pragma unroll
    for (int j = 0; j < 8; j++)
        #pragma unroll
        for (int q = 0; q < 4; q++) acc[j][q] = 0.0f;

    const uint32_t aRow = wm * 16 + (lane & 15);
    const uint32_t aKof = ((lane >> 4) << 3);
    const uint32_t bRow = wn * 64 + ((lane >> 4) << 3) + (lane & 7);
    const uint32_t bKof = ((lane >> 3) & 1) << 3;

    #pragma unroll
    for (int t = tid; t < 3072; t += 256) {
        const int sel = t >> 10;
        uint32_t dst; const __nv_bfloat16* src;
        if (sel == 0) {
            const int isLo = (t >> 9) & 1;
            const int u = t & 511, row = u >> 3, c8 = u & 7;
            dst = sb + (isLo ? OFF_AL : 0) + row * 144 + c8 * 16;
            src = (isLo ? Alo : Ahi) + (size_t)(bm * 64 + row) * KTOT + c8 * 8;
        } else {
            const int u = t & 1023, row = u >> 3, c8 = u & 7;
            dst = sb + (sel == 1 ? OFF_WH : (OFF_WH + 18432)) + row * 144 + c8 * 16;
            src = (sel == 1 ? Whi : Wlo) + (size_t)(bn * 128 + row) * KTOT + c8 * 8;
        }
        cp16(dst, src);
    }
    CP_COMMIT();

    for (int ch = 0; ch < nch; ch++) {
        if (ch + 1 < nch) {
            const uint32_t st = sb + ((ch + 1) & 1) * STAGE;
            const int kb = (ch + 1) * 64;
            #pragma unroll
            for (int t = tid; t < 3072; t += 256) {
                const int sel = t >> 10;
                uint32_t dst; const __nv_bfloat16* src;
                if (sel == 0) {
                    const int isLo = (t >> 9) & 1;
                    const int u = t & 511, row = u >> 3, c8 = u & 7;
                    dst = st + (isLo ? OFF_AL : 0) + row * 144 + c8 * 16;
                    src = (isLo ? Alo : Ahi) + (size_t)(bm * 64 + row) * KTOT + kb + c8 * 8;
                } else {
                    const int u = t & 1023, row = u >> 3, c8 = u & 7;
                    dst = st + (sel == 1 ? OFF_WH : (OFF_WH + 18432)) + row * 144 + c8 * 16;
                    src = (sel == 1 ? Whi : Wlo) + (size_t)(bn * 128 + row) * KTOT + kb + c8 * 8;
                }
                cp16(dst, src);
            }
            CP_COMMIT();
            CP_WAIT(1);
        } else {
            CP_WAIT(0);
        }
        __syncthreads();

        const uint32_t st = sb + (ch & 1) * STAGE;
        #pragma unroll
        for (int ks = 0; ks < 4; ks++) {
            const uint32_t aoff = st + (aRow * PITCH + ks * 16 + aKof) * 2;
            uint32_t ah[4], al[4];
            ldm_x4(ah[0], ah[1], ah[2], ah[3], aoff);
            ldm_x4(al[0], al[1], al[2], al[3], aoff + OFF_AL);
            #pragma unroll
            for (int nf4 = 0; nf4 < 4; nf4++) {
                const uint32_t boff = st + OFF_WH +
                    ((bRow + nf4 * 16) * PITCH + ks * 16 + bKof) * 2;
                uint32_t bh[4], bl[4];
                ldm_x4(bh[0], bh[1], bh[2], bh[3], boff);
                ldm_x4(bl[0], bl[1], bl[2], bl[3], boff + 18432);
                const int n0 = nf4 * 2;
                mma_bf16(acc[n0],     ah, bh);
                mma_bf16(acc[n0 + 1], ah, bh + 2);
                mma_bf16(acc[n0],     ah, bl);
                mma_bf16(acc[n0 + 1], ah, bl + 2);
                mma_bf16(acc[n0],     al, bh);
                mma_bf16(acc[n0 + 1], al, bh + 2);
            }
        }
        __syncthreads();
    }
}

// ---------------- fused qv + k GEMM (z-dispatch via blockIdx.x) ------------
__global__ __launch_bounds__(256, 2)
void gemm_qvk(const __nv_bfloat16* __restrict__ xnh, const __nv_bfloat16* __restrict__ xnl,
              const __nv_bfloat16* __restrict__ yh,  const __nv_bfloat16* __restrict__ yl,
              const __nv_bfloat16* __restrict__ wh,  const __nv_bfloat16* __restrict__ wl,
              const float* __restrict__ qv_b, const float* __restrict__ k_b,
              float* __restrict__ qout,
              __nv_bfloat16* __restrict__ vout, __nv_bfloat16* __restrict__ kout)
{
    extern __shared__ __align__(16) char dsm[];
    const uint32_t sb = smem_u32(dsm);
    const int bx = blockIdx.x, bm = blockIdx.y;
    float acc[8][4];
    if (bx < 2) gemm_core<128>(xnh, xnl, wh, wl, bm, bx, sb, acc);
    else        gemm_core<128>(yh, yl, wh + 32768, wl + 32768, bm, 0, sb, acc);

    const int tid = threadIdx.x, lane = tid & 31, wid = tid >> 5;
    const int wm = wid & 3, wn = wid >> 2;
    const int row0 = bm * 64 + wm * 16 + (lane >> 2);
    #pragma unroll
    for (int nf = 0; nf < 8; nf++) {
        const int coll = wn * 64 + nf * 8 + (lane & 3) * 2;
        if (bx == 0) {            // q: fp32, scaled
            float2 bi = *(const float2*)&qv_b[coll];
            float v0 = (acc[nf][0] + bi.x) * QSCALE;
            float v1 = (acc[nf][1] + bi.y) * QSCALE;
            float v2 = (acc[nf][2] + bi.x) * QSCALE;
            float v3 = (acc[nf][3] + bi.y) * QSCALE;
            *(float2*)&qout[(size_t)row0 * 128 + coll]       = make_float2(v0, v1);
            *(float2*)&qout[(size_t)(row0 + 8) * 128 + coll] = make_float2(v2, v3);
        } else if (bx == 1) {     // v: bf16
            float2 bi = *(const float2*)&qv_b[128 + coll];
            *(__nv_bfloat162*)&vout[(size_t)row0 * 128 + coll] =
                __floats2bfloat162_rn(acc[nf][0] + bi.x, acc[nf][1] + bi.y);
            *(__nv_bfloat162*)&vout[(size_t)(row0 + 8) * 128 + coll] =
                __floats2bfloat162_rn(acc[nf][2] + bi.x, acc[nf][3] + bi.y);
        } else {                  // k: bf16
            float2 bi = *(const float2*)&k_b[coll];
            *(__nv_bfloat162*)&kout[(size_t)row0 * 128 + coll] =
                __floats2bfloat162_rn(acc[nf][0] + bi.x, acc[nf][1] + bi.y);
            *(__nv_bfloat162*)&kout[(size_t)(row0 + 8) * 128 + coll] =
                __floats2bfloat162_rn(acc[nf][2] + bi.x, acc[nf][3] + bi.y);
        }
    }
}

// ---------------- proj GEMM + residual + fused LN2 ----------------
__global__ __launch_bounds__(256, 2)
void gemm_proj_ln(const __nv_bfloat16* __restrict__ Ahi, const __nv_bfloat16* __restrict__ Alo,
                  const __nv_bfloat16* __restrict__ Whi, const __nv_bfloat16* __restrict__ Wlo,
                  const float* __restrict__ bias, const float* __restrict__ res,
                  float* __restrict__ x2out,
                  const float* __restrict__ lnw, const float* __restrict__ lnb,
                  __nv_bfloat16* __restrict__ oh, __nv_bfloat16* __restrict__ ol)
{
    extern __shared__ __align__(16) char dsm[];
    const uint32_t sb = smem_u32(dsm);
    const int bm = blockIdx.y;
    float acc[8][4];
    gemm_core<128>(Ahi, Alo, Whi, Wlo, bm, 0, sb, acc);

    const int tid = threadIdx.x, lane = tid & 31, wid = tid >> 5;
    const int wm = wid & 3, wn = wid >> 2;
    float* xs = (float*)dsm;     // 64 x 132 (reuses stage smem)
    const int lr0 = wm * 16 + (lane >> 2);
    #pragma unroll
    for (int nf = 0; nf < 8; nf++) {
        const int coll = wn * 64 + nf * 8 + (lane & 3) * 2;
        float2 bi = *(const float2*)&bias[coll];
        float2 r0 = *(const float2*)&res[(size_t)(bm * 64 + lr0) * 128 + coll];
        float2 r1 = *(const float2*)&res[(size_t)(bm * 64 + lr0 + 8) * 128 + coll];
        float v0 = acc[nf][0] + bi.x + r0.x;
        float v1 = acc[nf][1] + bi.y + r0.y;
        float v2 = acc[nf][2] + bi.x + r1.x;
        float v3 = acc[nf][3] + bi.y + r1.y;
        xs[lr0 * 132 + coll] = v0;       xs[lr0 * 132 + coll + 1] = v1;
        xs[(lr0 + 8) * 132 + coll] = v2; xs[(lr0 + 8) * 132 + coll + 1] = v3;
        *(float2*)&x2out[(size_t)(bm * 64 + lr0) * 128 + coll]       = make_float2(v0, v1);
        *(float2*)&x2out[(size_t)(bm * 64 + lr0 + 8) * 128 + coll]   = make_float2(v2, v3);
    }
    __syncthreads();

    // LN over the 64 staged rows: 4 threads per row
    const int row = tid >> 2, q = tid & 3;
    float s = 0.0f, s2 = 0.0f;
    #pragma unroll
    for (int j = 0; j < 32; j++) {
        float v = xs[row * 132 + q * 32 + j];
        s += v; s2 += v * v;
    }
    s  += __shfl_xor_sync(0xffffffffu, s, 1);  s  += __shfl_xor_sync(0xffffffffu, s, 2);
    s2 += __shfl_xor_sync(0xffffffffu, s2, 1); s2 += __shfl_xor_sync(0xffffffffu, s2, 2);
    const float mu  = s * (1.0f / 128.0f);
    const float var = s2 * (1.0f / 128.0f) - mu * mu;
    const float rs = rsqrtf(var + 1e-5f);
    const int grow = bm * 64 + row;
    #pragma unroll
    for (int j = 0; j < 32; j++) {
        const int c = q * 32 + j;
        float r = (xs[row * 132 + c] - mu) * rs * lnw[c] + lnb[c];
        splitf(r, oh[(size_t)grow * 128 + c], ol[(size_t)grow * 128 + c]);
    }
}

// ---------------- fc1: GEMM + GELU -> hi/lo ----------------
__global__ __launch_bounds__(256, 2)
void gemm_gelu(const __nv_bfloat16* __restrict__ Ahi, const __nv_bfloat16* __restrict__ Alo,
               const __nv_bfloat16* __restrict__ Whi, const __nv_bfloat16* __restrict__ Wlo,
               const float* __restrict__ bias,
               __nv_bfloat16* __restrict__ oh, __nv_bfloat16* __restrict__ ol)
{
    extern __shared__ __align__(16) char dsm[];
    const uint32_t sb = smem_u32(dsm);
    const int bn = blockIdx.x, bm = blockIdx.y;
    float acc[8][4];
    gemm_core<128>(Ahi, Alo, Whi, Wlo, bm, bn, sb, acc);

    const int tid = threadIdx.x, lane = tid & 31, wid = tid >> 5;
    const int wm = wid & 3, wn = wid >> 2;
    const int row0 = bm * 64 + wm * 16 + (lane >> 2);
    #pragma unroll
    for (int nf = 0; nf < 8; nf++) {
        const int col = bn * 128 + wn * 64 + nf * 8 + (lane & 3) * 2;
        float2 bi = *(const float2*)&bias[col];
        float v[4];
        v[0] = acc[nf][0] + bi.x; v[1] = acc[nf][1] + bi.y;
        v[2] = acc[nf][2] + bi.x; v[3] = acc[nf][3] + bi.y;
        #pragma unroll
        for (int e = 0; e < 4; e++)
            v[e] = 0.5f * v[e] * (1.0f + erff(v[e] * 0.70710678118654752f));
        const size_t o0 = (size_t)row0 * 512 + col;
        const size_t o1 = (size_t)(row0 + 8) * 512 + col;
        __nv_bfloat16 h, l;
        splitf(v[0], h, l); oh[o0]     = h; ol[o0]     = l;
        splitf(v[1], h, l); oh[o0 + 1] = h; ol[o0 + 1] = l;
        splitf(v[2], h, l); oh[o1]     = h; ol[o1]     = l;
        splitf(v[3], h, l); oh[o1 + 1] = h; ol[o1 + 1] = l;
    }
}

// ---------------- fc2: GEMM + residual -> out ----------------
__global__ __launch_bounds__(256, 2)
void gemm_res2(const __nv_bfloat16* __restrict__ Ahi, const __nv_bfloat16* __restrict__ Alo,
               const __nv_bfloat16* __restrict__ Whi, const __nv_bfloat16* __restrict__ Wlo,
               const float* __restrict__ bias, const float* __restrict__ res,
               float* __restrict__ outf)
{
    extern __shared__ __align__(16) char dsm[];
    const uint32_t sb = smem_u32(dsm);
    const int bm = blockIdx.y;
    float acc[8][4];
    gemm_core<512>(Ahi, Alo, Whi, Wlo, bm, 0, sb, acc);

    const int tid = threadIdx.x, lane = tid & 31, wid = tid >> 5;
    const int wm = wid & 3, wn = wid >> 2;
    const int row0 = bm * 64 + wm * 16 + (lane >> 2);
    #pragma unroll
    for (int nf = 0; nf < 8; nf++) {
        const int col = wn * 64 + nf * 8 + (lane & 3) * 2;
        float2 bi = *(const float2*)&bias[col];
        float2 r0 = *(const float2*)&res[(size_t)row0 * 128 + col];
        float2 r1 = *(const float2*)&res[(size_t)(row0 + 8) * 128 + col];
        *(float2*)&outf[(size_t)row0 * 128 + col] =
            make_float2(acc[nf][0] + bi.x + r0.x, acc[nf][1] + bi.y + r0.y);
        *(float2*)&outf[(size_t)(row0 + 8) * 128 + col] =
            make_float2(acc[nf][2] + bi.x + r1.x, acc[nf][3] + bi.y + r1.y);
    }
}

// ------- neighborhood attention: bf16 k/v in smem, pitch-40 rows ----------
#define NBW 22
#define NBH 14
#define NBR (NBW * NBH)   // 308
#define KVP 40            // bf16 pitch per row (80B, conflict-free for uint4)

__global__ __launch_bounds__(128)
void attn_kernel(const float* __restrict__ qbuf,
                 const __nv_bfloat16* __restrict__ vb,
                 const __nv_bfloat16* __restrict__ kb,
                 const float* __restrict__ rpb,
                 __nv_bfloat16* __restrict__ oh,
                 __nv_bfloat16* __restrict__ ol)
{
    __shared__ __align__(16) __nv_bfloat16 kv_s[NBR * KVP];   // 24640 B
    __shared__ float rpb_s[RPBW * RPBW];

    const int hd = blockIdx.z;
    const int bw = blockIdx.x * 16, bh = blockIdx.y * 8;
    const int tid = threadIdx.x;
    const int px = tid & 15, py = tid >> 4;
    const int h = bh + py, w = bw + px;
    const int o_h = min(max(bh - 3, 0), Hdim - NBH);
    const int o_w = min(max(bw - 3, 0), Wdim - NBW);

    for (int i = tid; i < RPBW * RPBW; i += 128) rpb_s[i] = rpb[hd * RPBW * RPBW + i];

    // stage k (bf16, 4 uint4 per row)
    for (int idx = tid; idx < NBR * 4; idx += 128) {
        const int rr = idx >> 2, j = idx & 3;
        const int gh = o_h + rr / NBW, gw = o_w + rr % NBW;
        *(uint4*)&kv_s[rr * KVP + j * 8] =
            *(const uint4*)&kb[(size_t)(gh * Wdim + gw) * Cdim + hd * HD + j * 8];
    }
    __syncthreads();

    float qf[32];
    {
        const float4* qp = (const float4*)&qbuf[(size_t)(h * Wdim + w) * Cdim + hd * HD];
        #pragma unroll
        for (int j = 0; j < 8; j++) {
            float4 t = qp[j];
            qf[j * 4] = t.x; qf[j * 4 + 1] = t.y; qf[j * 4 + 2] = t.z; qf[j * 4 + 3] = t.w;
        }
    }

    const int sh = min(max(h - 3, 0), Hdim - KW);
    const int sw = min(max(w - 3, 0), Wdim - KW);
    const int lr0 = sh - o_h, lc0 = sw - o_w;
    const int rh0 = sh - h + 6, rw0 = sw - w + 6;

    float p[KK];
    #pragma unroll
    for (int a = 0; a < KW; a++) {
        #pragma unroll
        for (int c = 0; c < KW; c++) {
            const uint4* kp = (const uint4*)&kv_s[((lr0 + a) * NBW + lc0 + c) * KVP];
            float d = 0.0f;
            #pragma unroll
            for (int j = 0; j < 4; j++) {
                uint4 t = kp[j];
                float2 f;
                f = __bfloat1622float2(*(__nv_bfloat162*)&t.x);
                d = fmaf(qf[j*8+0], f.x, d); d = fmaf(qf[j*8+1], f.y, d);
                f = __bfloat1622float2(*(__nv_bfloat162*)&t.y);
                d = fmaf(qf[j*8+2], f.x, d); d = fmaf(qf[j*8+3], f.y, d);
                f = __bfloat1622float2(*(__nv_bfloat162*)&t.z);
                d = fmaf(qf[j*8+4], f.x, d); d = fmaf(qf[j*8+5], f.y, d);
                f = __bfloat1622float2(*(__nv_bfloat162*)&t.w);
                d = fmaf(qf[j*8+6], f.x, d); d = fmaf(qf[j*8+7], f.y, d);
            }
            p[a * KW + c] = d + rpb_s[(rh0 + a) * RPBW + rw0 + c];
        }
    }

    float mx = -1e30f;
    #pragma unroll
    for (int n = 0; n < KK; n++) mx = fmaxf(mx, p[n]);
    float ssum = 0.0f;
    #pragma unroll
    for (int n = 0; n < KK; n++) { p[n] = __expf(p[n] - mx); ssum += p[n]; }
    const float inv = __fdividef(1.0f, ssum);
    __syncthreads();

    // stage v into same buffer
    for (int idx = tid; idx < NBR * 4; idx += 128) {
        const int rr = idx >> 2, j = idx & 3;
        const int gh = o_h + rr / NBW, gw = o_w + rr % NBW;
        *(uint4*)&kv_s[rr * KVP + j * 8] =
            *(const uint4*)&vb[(size_t)(gh * Wdim + gw) * Cdim + hd * HD + j * 8];
    }
    __syncthreads();

    float acc[32];
    #pragma unroll
    for (int j = 0; j < 32; j++) acc[j] = 0.0f;
    #pragma unroll
    for (int a = 0; a < KW; a++) {
        #pragma unroll
        for (int c = 0; c < KW; c++) {
            const float pr = p[a * KW + c] * inv;
            const uint4* vp = (const uint4*)&kv_s[((lr0 + a) * NBW + lc0 + c) * KVP];
            #pragma unroll
            for (int j = 0; j < 4; j++) {
                uint4 t = vp[j];
                float2 f;
                f = __bfloat1622float2(*(__nv_bfloat162*)&t.x);
                acc[j*8+0] = fmaf(pr, f.x, acc[j*8+0]); acc[j*8+1] = fmaf(pr, f.y, acc[j*8+1]);
                f = __bfloat1622float2(*(__nv_bfloat162*)&t.y);
                acc[j*8+2] = fmaf(pr, f.x, acc[j*8+2]); acc[j*8+3] = fmaf(pr, f.y, acc[j*8+3]);
                f = __bfloat1622float2(*(__nv_bfloat162*)&t.z);
                acc[j*8+4] = fmaf(pr, f.x, acc[j*8+4]); acc[j*8+5] = fmaf(pr, f.y, acc[j*8+5]);
                f = __bfloat1622float2(*(__nv_bfloat162*)&t.w);
                acc[j*8+6] = fmaf(pr, f.x, acc[j*8+6]); acc[j*8+7] = fmaf(pr, f.y, acc[j*8+7]);
            }
        }
    }
    const size_t base = (size_t)(h * Wdim + w) * Cdim + hd * HD;
    #pragma unroll
    for (int j = 0; j < 32; j++) {
        __nv_bfloat16 hh, ll;
        splitf(acc[j], hh, ll);
        oh[base + j] = hh; ol[base + j] = ll;
    }
}

// ---------------- launch -----------------
extern "C" void kernel_launch(void* const* d_in, const int* in_sizes, int n_in,
                              void* d_out, int out_size)
{
    const float* x      = (const float*)d_in[0];
    const float* y      = (const float*)d_in[1];
    const float* qv_w   = (const float*)d_in[2];
    const float* qv_b   = (const float*)d_in[3];
    const float* k_w    = (const float*)d_in[4];
    const float* k_b    = (const float*)d_in[5];
    const float* rpb    = (const float*)d_in[6];
    const float* proj_w = (const float*)d_in[7];
    const float* proj_b = (const float*)d_in[8];
    const float* n1_w   = (const float*)d_in[9];
    const float* n1_b   = (const float*)d_in[10];
    const float* n2_w   = (const float*)d_in[11];
    const float* n2_b   = (const float*)d_in[12];
    const float* fc1_w  = (const float*)d_in[13];
    const float* fc1_b  = (const float*)d_in[14];
    const float* fc2_w  = (const float*)d_in[15];
    const float* fc2_b  = (const float*)d_in[16];
    float* out = (float*)d_out;

    float *p_q, *p_x2;
    __nv_bfloat16 *p_vb, *p_kb, *xnh, *xnl, *yh, *yl, *ath, *atl, *hh, *hl, *wh, *wl;
    cudaGetSymbolAddress((void**)&p_q,  g_q);
    cudaGetSymbolAddress((void**)&p_x2, g_x2);
    cudaGetSymbolAddress((void**)&p_vb, g_vb);
    cudaGetSymbolAddress((void**)&p_kb, g_kb);
    cudaGetSymbolAddress((void**)&xnh, s_xn_hi);
    cudaGetSymbolAddress((void**)&xnl, s_xn_lo);
    cudaGetSymbolAddress((void**)&yh,  s_y_hi);
    cudaGetSymbolAddress((void**)&yl,  s_y_lo);
    cudaGetSymbolAddress((void**)&ath, s_att_hi);
    cudaGetSymbolAddress((void**)&atl, s_att_lo);
    cudaGetSymbolAddress((void**)&hh,  s_h_hi);
    cudaGetSymbolAddress((void**)&hl,  s_h_lo);
    cudaGetSymbolAddress((void**)&wh,  s_w_hi);
    cudaGetSymbolAddress((void**)&wl,  s_w_lo);

    cudaFuncSetAttribute(gemm_qvk,     cudaFuncAttributeMaxDynamicSharedMemorySize, GSMEM);
    cudaFuncSetAttribute(gemm_proj_ln, cudaFuncAttributeMaxDynamicSharedMemorySize, GSMEM);
    cudaFuncSetAttribute(gemm_gelu,    cudaFuncAttributeMaxDynamicSharedMemorySize, GSMEM);
    cudaFuncSetAttribute(gemm_res2,    cudaFuncAttributeMaxDynamicSharedMemorySize, GSMEM);

    // 1) prep: LN1(x) + split(y) + split(weights)
    prep_kernel<<<12672, 256>>>(x, n1_w, n1_b, y, qv_w, k_w, proj_w, fc1_w, fc2_w,
                                xnh, xnl, yh, yl, wh, wl);

    // 2) fused qv + k GEMMs
    gemm_qvk<<<dim3(3, NPIX / 64), 256, GSMEM>>>(
        xnh, xnl, yh, yl, wh, wl, qv_b, k_b, p_q, p_vb, p_kb);

    // 3) neighborhood attention
    attn_kernel<<<dim3(Wdim / 16, Hdim / 8, HEADS), 128>>>(p_q, p_vb, p_kb, rpb, ath, atl);

    // 4) proj GEMM + residual + LN2 (fused)
    gemm_proj_ln<<<dim3(1, NPIX / 64), 256, GSMEM>>>(
        ath, atl, wh + 49152, wl + 49152, proj_b, x, p_x2, n2_w, n2_b, xnh, xnl);

    // 5) fc1 + GELU
    gemm_gelu<<<dim3(4, NPIX / 64), 256, GSMEM>>>(
        xnh, xnl, wh + 65536, wl + 65536, fc1_b, hh, hl);

    // 6) fc2 + residual -> out
    gemm_res2<<<dim3(1, NPIX / 64), 256, GSMEM>>>(
        hh, hl, wh + 131072, wl + 131072, fc2_b, p_x2, out);
}

// round 7
// speedup vs baseline: 1.3242x; 1.3242x over previous
#include <cuda_runtime.h>
#include <cuda_bf16.h>
#include <math.h>
#include <stdint.h>

#define Hdim 128
#define Wdim 128
#define Cdim 128
#define NPIX (Hdim * Wdim)
#define HEADS 4
#define HD 32
#define KW 7
#define KK 49
#define RPBW 13
#define QSCALE 0.17677669529663689f

// ---------------- scratch ----------------
__device__ float g_q  [NPIX * Cdim];              // q fp32 (scaled)
__device__ float g_x2 [NPIX * Cdim];              // x + proj(attn)
__device__ __nv_bfloat16 g_vb [NPIX * Cdim];      // v bf16
__device__ __nv_bfloat16 g_kb [NPIX * Cdim];      // k bf16
__device__ __nv_bfloat16 s_xn_hi[NPIX * Cdim];
__device__ __nv_bfloat16 s_xn_lo[NPIX * Cdim];
__device__ __nv_bfloat16 s_y_hi [NPIX * Cdim];
__device__ __nv_bfloat16 s_y_lo [NPIX * Cdim];
__device__ __nv_bfloat16 s_att_hi[NPIX * Cdim];
__device__ __nv_bfloat16 s_att_lo[NPIX * Cdim];
__device__ __nv_bfloat16 s_h_hi [NPIX * 512];
__device__ __nv_bfloat16 s_h_lo [NPIX * 512];
// weights: qv@0 (32768), k@32768, proj@49152, fc1@65536, fc2@131072
__device__ __nv_bfloat16 s_w_hi[196608];
__device__ __nv_bfloat16 s_w_lo[196608];

// ---------------- helpers ----------------
__device__ __forceinline__ uint32_t smem_u32(const void* p) {
    uint32_t a;
    asm("{ .reg .u64 t; cvta.to.shared.u64 t, %1; cvt.u32.u64 %0, t; }" : "=r"(a) : "l"(p));
    return a;
}
__device__ __forceinline__ void ldm_x4(uint32_t& r0, uint32_t& r1, uint32_t& r2, uint32_t& r3,
                                       uint32_t addr) {
    asm volatile("ldmatrix.sync.aligned.m8n8.x4.shared.b16 {%0,%1,%2,%3}, [%4];"
        : "=r"(r0), "=r"(r1), "=r"(r2), "=r"(r3) : "r"(addr));
}
__device__ __forceinline__ void mma_bf16(float* d, const uint32_t* a, const uint32_t* b) {
    asm volatile("mma.sync.aligned.m16n8k16.row.col.f32.bf16.bf16.f32 "
        "{%0,%1,%2,%3}, {%4,%5,%6,%7}, {%8,%9}, {%0,%1,%2,%3};"
        : "+f"(d[0]), "+f"(d[1]), "+f"(d[2]), "+f"(d[3])
        : "r"(a[0]), "r"(a[1]), "r"(a[2]), "r"(a[3]), "r"(b[0]), "r"(b[1]));
}
__device__ __forceinline__ void cp16(uint32_t dst, const void* src) {
    asm volatile("cp.async.ca.shared.global [%0], [%1], 16;" :: "r"(dst), "l"(src));
}
#define CP_COMMIT() asm volatile("cp.async.commit_group;" ::: "memory")
#define CP_WAIT(n)  asm volatile("cp.async.wait_group %0;" :: "n"(n) : "memory")
__device__ __forceinline__ void splitf(float a, __nv_bfloat16& h, __nv_bfloat16& l) {
    h = __float2bfloat16(a);
    l = __float2bfloat16(a - __bfloat162float(h));
}
__device__ __forceinline__ uint32_t pack_hi(float a, float b) {
    __nv_bfloat162 t = __floats2bfloat162_rn(a, b);
    return *(uint32_t*)&t;
}

// ---------------- prep: LN1 + split_y + split_w, one launch ----------------
__global__ void prep_kernel(const float* __restrict__ x,
                            const float* __restrict__ n1w, const float* __restrict__ n1b,
                            const float* __restrict__ y,
                            const float* __restrict__ qvw, const float* __restrict__ kw,
                            const float* __restrict__ pw,  const float* __restrict__ f1,
                            const float* __restrict__ f2,
                            __nv_bfloat16* __restrict__ xnh, __nv_bfloat16* __restrict__ xnl,
                            __nv_bfloat16* __restrict__ yh,  __nv_bfloat16* __restrict__ yl,
                            __nv_bfloat16* __restrict__ wh,  __nv_bfloat16* __restrict__ wl)
{
    const int b = blockIdx.x, tid = threadIdx.x;
    if (b < 8192) {
        const int row = b * 2 + (tid >> 7);
        const int r = tid & 127;
        float v = x[row * Cdim + r];
        float s = v, s2 = v * v;
        #pragma unroll
        for (int o = 16; o; o >>= 1) {
            s  += __shfl_xor_sync(0xffffffffu, s,  o);
            s2 += __shfl_xor_sync(0xffffffffu, s2, o);
        }
        __shared__ float ss[8], ss2[8];
        const int wrp = tid >> 5;
        if ((tid & 31) == 0) { ss[wrp] = s; ss2[wrp] = s2; }
        __syncthreads();
        const int base = (tid >> 7) * 4;
        s  = ss[base]  + ss[base + 1]  + ss[base + 2]  + ss[base + 3];
        s2 = ss2[base] + ss2[base + 1] + ss2[base + 2] + ss2[base + 3];
        float mu  = s * (1.0f / Cdim);
        float var = s2 * (1.0f / Cdim) - mu * mu;
        float rr = (v - mu) * rsqrtf(var + 1e-5f) * n1w[r] + n1b[r];
        splitf(rr, xnh[row * Cdim + r], xnl[row * Cdim + r]);
    } else if (b < 12288) {
        const int i = (b - 8192) * 512 + tid * 2;
        splitf(y[i],     yh[i],     yl[i]);
        splitf(y[i + 1], yh[i + 1], yl[i + 1]);
    } else {
        const int wi = (b - 12288) * 512 + tid * 2;
        #pragma unroll
        for (int e = 0; e < 2; e++) {
            int q = wi + e;
            if (q < 196608) {
                float v;
                if      (q < 32768)  v = qvw[q];
                else if (q < 49152)  v = kw [q - 32768];
                else if (q < 65536)  v = pw [q - 49152];
                else if (q < 131072) v = f1 [q - 65536];
                else                 v = f2 [q - 131072];
                splitf(v, wh[q], wl[q]);
            }
        }
    }
}

// ---------------- LN2 (standalone, fp32 in -> hi/lo bf16) ----------------
__global__ void ln_kernel(const float* __restrict__ x,
                          const float* __restrict__ w,
                          const float* __restrict__ b,
                          __nv_bfloat16* __restrict__ oh,
                          __nv_bfloat16* __restrict__ ol)
{
    int row = blockIdx.x;
    int tid = threadIdx.x;
    float v = x[row * Cdim + tid];
    float s = v, s2 = v * v;
    #pragma unroll
    for (int o = 16; o; o >>= 1) {
        s  += __shfl_xor_sync(0xffffffffu, s,  o);
        s2 += __shfl_xor_sync(0xffffffffu, s2, o);
    }
    __shared__ float ss[4], ss2[4];
    if ((tid & 31) == 0) { ss[tid >> 5] = s; ss2[tid >> 5] = s2; }
    __syncthreads();
    s  = ss[0] + ss[1] + ss[2] + ss[3];
    s2 = ss2[0] + ss2[1] + ss2[2] + ss2[3];
    float mu  = s * (1.0f / Cdim);
    float var = s2 * (1.0f / Cdim) - mu * mu;
    float r = (v - mu) * rsqrtf(var + 1e-5f) * w[tid] + b[tid];
    splitf(r, oh[row * Cdim + tid], ol[row * Cdim + tid]);
}

// ---------------- shared GEMM core: 64x128 tile, cp.async 2-stage ----------
// Per k16-step: load ALL fragments, then 24 MMAs pass-major (acc reuse dist 8).
#define PITCH 72
#define OFF_AL 9216
#define OFF_WH 18432
#define STAGE  55296
#define GSMEM  (2 * STAGE)

template <int KTOT>
__device__ __forceinline__ void gemm_core(
    const __nv_bfloat16* __restrict__ Ahi, const __nv_bfloat16* __restrict__ Alo,
    const __nv_bfloat16* __restrict__ Whi, const __nv_bfloat16* __restrict__ Wlo,
    int bm, int bn, uint32_t sb, float acc[8][4])
{
    const int tid = threadIdx.x, lane = tid & 31, wid = tid >> 5;
    const int wm = wid & 3, wn = wid >> 2;
    const int nch = KTOT / 64;

    #pragma unroll
    for (int j = 0; j < 8; j++)
        #pragma unroll
        for (int q = 0; q < 4; q++) acc[j][q] = 0.0f;

    const uint32_t aRow = wm * 16 + (lane & 15);
    const uint32_t aKof = ((lane >> 4) << 3);
    const uint32_t bRow = wn * 64 + ((lane >> 4) << 3) + (lane & 7);
    const uint32_t bKof = ((lane >> 3) & 1) << 3;

    #pragma unroll
    for (int t = tid; t < 3072; t += 256) {
        const int sel = t >> 10;
        uint32_t dst; const __nv_bfloat16* src;
        if (sel == 0) {
            const int isLo = (t >> 9) & 1;
            const int u = t & 511, row = u >> 3, c8 = u & 7;
            dst = sb + (isLo ? OFF_AL : 0) + row * 144 + c8 * 16;
            src = (isLo ? Alo : Ahi) + (size_t)(bm * 64 + row) * KTOT + c8 * 8;
        } else {
            const int u = t & 1023, row = u >> 3, c8 = u & 7;
            dst = sb + (sel == 1 ? OFF_WH : (OFF_WH + 18432)) + row * 144 + c8 * 16;
            src = (sel == 1 ? Whi : Wlo) + (size_t)(bn * 128 + row) * KTOT + c8 * 8;
        }
        cp16(dst, src);
    }
    CP_COMMIT();

    for (int ch = 0; ch < nch; ch++) {
        if (ch + 1 < nch) {
            const uint32_t st = sb + ((ch + 1) & 1) * STAGE;
            const int kb = (ch + 1) * 64;
            #pragma unroll
            for (int t = tid; t < 3072; t += 256) {
                const int sel = t >> 10;
                uint32_t dst; const __nv_bfloat16* src;
                if (sel == 0) {
                    const int isLo = (t >> 9) & 1;
                    const int u = t & 511, row = u >> 3, c8 = u & 7;
                    dst = st + (isLo ? OFF_AL : 0) + row * 144 + c8 * 16;
                    src = (isLo ? Alo : Ahi) + (size_t)(bm * 64 + row) * KTOT + kb + c8 * 8;
                } else {
                    const int u = t & 1023, row = u >> 3, c8 = u & 7;
                    dst = st + (sel == 1 ? OFF_WH : (OFF_WH + 18432)) + row * 144 + c8 * 16;
                    src = (sel == 1 ? Whi : Wlo) + (size_t)(bn * 128 + row) * KTOT + kb + c8 * 8;
                }
                cp16(dst, src);
            }
            CP_COMMIT();
            CP_WAIT(1);
        } else {
            CP_WAIT(0);
        }
        __syncthreads();

        const uint32_t st = sb + (ch & 1) * STAGE;
        #pragma unroll
        for (int ks = 0; ks < 4; ks++) {
            const uint32_t aoff = st + (aRow * PITCH + ks * 16 + aKof) * 2;
            uint32_t ah[4], al[4];
            ldm_x4(ah[0], ah[1], ah[2], ah[3], aoff);
            ldm_x4(al[0], al[1], al[2], al[3], aoff + OFF_AL);
            uint32_t bh[4][4], bl[4][4];
            #pragma unroll
            for (int nf4 = 0; nf4 < 4; nf4++) {
                const uint32_t boff = st + OFF_WH +
                    ((bRow + nf4 * 16) * PITCH + ks * 16 + bKof) * 2;
                ldm_x4(bh[nf4][0], bh[nf4][1], bh[nf4][2], bh[nf4][3], boff);
                ldm_x4(bl[nf4][0], bl[nf4][1], bl[nf4][2], bl[nf4][3], boff + 18432);
            }
            // pass-major: 8 independent MMAs per pass
            #pragma unroll
            for (int nf4 = 0; nf4 < 4; nf4++) {
                mma_bf16(acc[nf4 * 2],     ah, bh[nf4]);
                mma_bf16(acc[nf4 * 2 + 1], ah, bh[nf4] + 2);
            }
            #pragma unroll
            for (int nf4 = 0; nf4 < 4; nf4++) {
                mma_bf16(acc[nf4 * 2],     ah, bl[nf4]);
                mma_bf16(acc[nf4 * 2 + 1], ah, bl[nf4] + 2);
            }
            #pragma unroll
            for (int nf4 = 0; nf4 < 4; nf4++) {
                mma_bf16(acc[nf4 * 2],     al, bh[nf4]);
                mma_bf16(acc[nf4 * 2 + 1], al, bh[nf4] + 2);
            }
        }
        __syncthreads();
    }
}

// ---------------- fused qv + k GEMM ----------------
__global__ __launch_bounds__(256, 2)
void gemm_qvk(const __nv_bfloat16* __restrict__ xnh, const __nv_bfloat16* __restrict__ xnl,
              const __nv_bfloat16* __restrict__ yh,  const __nv_bfloat16* __restrict__ yl,
              const __nv_bfloat16* __restrict__ wh,  const __nv_bfloat16* __restrict__ wl,
              const float* __restrict__ qv_b, const float* __restrict__ k_b,
              float* __restrict__ qout,
              __nv_bfloat16* __restrict__ vout, __nv_bfloat16* __restrict__ kout)
{
    extern __shared__ __align__(16) char dsm[];
    const uint32_t sb = smem_u32(dsm);
    const int bx = blockIdx.x, bm = blockIdx.y;
    float acc[8][4];
    if (bx < 2) gemm_core<128>(xnh, xnl, wh, wl, bm, bx, sb, acc);
    else        gemm_core<128>(yh, yl, wh + 32768, wl + 32768, bm, 0, sb, acc);

    const int tid = threadIdx.x, lane = tid & 31, wid = tid >> 5;
    const int wm = wid & 3, wn = wid >> 2;
    const int row0 = bm * 64 + wm * 16 + (lane >> 2);
    #pragma unroll
    for (int nf = 0; nf < 8; nf++) {
        const int coll = wn * 64 + nf * 8 + (lane & 3) * 2;
        if (bx == 0) {
            float2 bi = *(const float2*)&qv_b[coll];
            *(float2*)&qout[(size_t)row0 * 128 + coll] =
                make_float2((acc[nf][0] + bi.x) * QSCALE, (acc[nf][1] + bi.y) * QSCALE);
            *(float2*)&qout[(size_t)(row0 + 8) * 128 + coll] =
                make_float2((acc[nf][2] + bi.x) * QSCALE, (acc[nf][3] + bi.y) * QSCALE);
        } else if (bx == 1) {
            float2 bi = *(const float2*)&qv_b[128 + coll];
            *(uint32_t*)&vout[(size_t)row0 * 128 + coll]       = pack_hi(acc[nf][0] + bi.x, acc[nf][1] + bi.y);
            *(uint32_t*)&vout[(size_t)(row0 + 8) * 128 + coll] = pack_hi(acc[nf][2] + bi.x, acc[nf][3] + bi.y);
        } else {
            float2 bi = *(const float2*)&k_b[coll];
            *(uint32_t*)&kout[(size_t)row0 * 128 + coll]       = pack_hi(acc[nf][0] + bi.x, acc[nf][1] + bi.y);
            *(uint32_t*)&kout[(size_t)(row0 + 8) * 128 + coll] = pack_hi(acc[nf][2] + bi.x, acc[nf][3] + bi.y);
        }
    }
}

// ---------------- proj GEMM + residual (plain, coalesced) ----------------
__global__ __launch_bounds__(256, 2)
void gemm_proj(const __nv_bfloat16* __restrict__ Ahi, const __nv_bfloat16* __restrict__ Alo,
               const __nv_bfloat16* __restrict__ Whi, const __nv_bfloat16* __restrict__ Wlo,
               const float* __restrict__ bias, const float* __restrict__ res,
               float* __restrict__ x2out)
{
    extern __shared__ __align__(16) char dsm[];
    const uint32_t sb = smem_u32(dsm);
    const int bm = blockIdx.y;
    float acc[8][4];
    gemm_core<128>(Ahi, Alo, Whi, Wlo, bm, 0, sb, acc);

    const int tid = threadIdx.x, lane = tid & 31, wid = tid >> 5;
    const int wm = wid & 3, wn = wid >> 2;
    const int row0 = bm * 64 + wm * 16 + (lane >> 2);
    #pragma unroll
    for (int nf = 0; nf < 8; nf++) {
        const int col = wn * 64 + nf * 8 + (lane & 3) * 2;
        float2 bi = *(const float2*)&bias[col];
        float2 r0 = *(const float2*)&res[(size_t)row0 * 128 + col];
        float2 r1 = *(const float2*)&res[(size_t)(row0 + 8) * 128 + col];
        *(float2*)&x2out[(size_t)row0 * 128 + col] =
            make_float2(acc[nf][0] + bi.x + r0.x, acc[nf][1] + bi.y + r0.y);
        *(float2*)&x2out[(size_t)(row0 + 8) * 128 + col] =
            make_float2(acc[nf][2] + bi.x + r1.x, acc[nf][3] + bi.y + r1.y);
    }
}

// ---------------- fc1: GEMM + GELU -> hi/lo ----------------
__global__ __launch_bounds__(256, 2)
void gemm_gelu(const __nv_bfloat16* __restrict__ Ahi, const __nv_bfloat16* __restrict__ Alo,
               const __nv_bfloat16* __restrict__ Whi, const __nv_bfloat16* __restrict__ Wlo,
               const float* __restrict__ bias,
               __nv_bfloat16* __restrict__ oh, __nv_bfloat16* __restrict__ ol)
{
    extern __shared__ __align__(16) char dsm[];
    const uint32_t sb = smem_u32(dsm);
    const int bn = blockIdx.x, bm = blockIdx.y;
    float acc[8][4];
    gemm_core<128>(Ahi, Alo, Whi, Wlo, bm, bn, sb, acc);

    const int tid = threadIdx.x, lane = tid & 31, wid = tid >> 5;
    const int wm = wid & 3, wn = wid >> 2;
    const int row0 = bm * 64 + wm * 16 + (lane >> 2);
    #pragma unroll
    for (int nf = 0; nf < 8; nf++) {
        const int col = bn * 128 + wn * 64 + nf * 8 + (lane & 3) * 2;
        float2 bi = *(const float2*)&bias[col];
        float v[4];
        v[0] = acc[nf][0] + bi.x; v[1] = acc[nf][1] + bi.y;
        v[2] = acc[nf][2] + bi.x; v[3] = acc[nf][3] + bi.y;
        #pragma unroll
        for (int e = 0; e < 4; e++)
            v[e] = 0.5f * v[e] * (1.0f + erff(v[e] * 0.70710678118654752f));
        __nv_bfloat16 h0, l0, h1, l1;
        const size_t o0 = (size_t)row0 * 512 + col;
        const size_t o1 = (size_t)(row0 + 8) * 512 + col;
        splitf(v[0], h0, l0); splitf(v[1], h1, l1);
        *(uint32_t*)&oh[o0] = ((uint32_t)*(uint16_t*)&h1 << 16) | *(uint16_t*)&h0;
        *(uint32_t*)&ol[o0] = ((uint32_t)*(uint16_t*)&l1 << 16) | *(uint16_t*)&l0;
        splitf(v[2], h0, l0); splitf(v[3], h1, l1);
        *(uint32_t*)&oh[o1] = ((uint32_t)*(uint16_t*)&h1 << 16) | *(uint16_t*)&h0;
        *(uint32_t*)&ol[o1] = ((uint32_t)*(uint16_t*)&l1 << 16) | *(uint16_t*)&l0;
    }
}

// ---------------- fc2: GEMM + residual -> out ----------------
__global__ __launch_bounds__(256, 2)
void gemm_res2(const __nv_bfloat16* __restrict__ Ahi, const __nv_bfloat16* __restrict__ Alo,
               const __nv_bfloat16* __restrict__ Whi, const __nv_bfloat16* __restrict__ Wlo,
               const float* __restrict__ bias, const float* __restrict__ res,
               float* __restrict__ outf)
{
    extern __shared__ __align__(16) char dsm[];
    const uint32_t sb = smem_u32(dsm);
    const int bm = blockIdx.y;
    float acc[8][4];
    gemm_core<512>(Ahi, Alo, Whi, Wlo, bm, 0, sb, acc);

    const int tid = threadIdx.x, lane = tid & 31, wid = tid >> 5;
    const int wm = wid & 3, wn = wid >> 2;
    const int row0 = bm * 64 + wm * 16 + (lane >> 2);
    #pragma unroll
    for (int nf = 0; nf < 8; nf++) {
        const int col = wn * 64 + nf * 8 + (lane & 3) * 2;
        float2 bi = *(const float2*)&bias[col];
        float2 r0 = *(const float2*)&res[(size_t)row0 * 128 + col];
        float2 r1 = *(const float2*)&res[(size_t)(row0 + 8) * 128 + col];
        *(float2*)&outf[(size_t)row0 * 128 + col] =
            make_float2(acc[nf][0] + bi.x + r0.x, acc[nf][1] + bi.y + r0.y);
        *(float2*)&outf[(size_t)(row0 + 8) * 128 + col] =
            make_float2(acc[nf][2] + bi.x + r1.x, acc[nf][3] + bi.y + r1.y);
    }
}

// ------- neighborhood attention: bf16 k/v in smem, pitch-40 rows ----------
#define NBW 22
#define NBH 14
#define NBR (NBW * NBH)
#define KVP 40

__global__ __launch_bounds__(128)
void attn_kernel(const float* __restrict__ qbuf,
                 const __nv_bfloat16* __restrict__ vb,
                 const __nv_bfloat16* __restrict__ kb,
                 const float* __restrict__ rpb,
                 __nv_bfloat16* __restrict__ oh,
                 __nv_bfloat16* __restrict__ ol)
{
    __shared__ __align__(16) __nv_bfloat16 kv_s[NBR * KVP];
    __shared__ float rpb_s[RPBW * RPBW];

    const int hd = blockIdx.z;
    const int bw = blockIdx.x * 16, bh = blockIdx.y * 8;
    const int tid = threadIdx.x;
    const int px = tid & 15, py = tid >> 4;
    const int h = bh + py, w = bw + px;
    const int o_h = min(max(bh - 3, 0), Hdim - NBH);
    const int o_w = min(max(bw - 3, 0), Wdim - NBW);

    for (int i = tid; i < RPBW * RPBW; i += 128) rpb_s[i] = rpb[hd * RPBW * RPBW + i];

    for (int idx = tid; idx < NBR * 4; idx += 128) {
        const int rr = idx >> 2, j = idx & 3;
        const int gh = o_h + rr / NBW, gw = o_w + rr % NBW;
        *(uint4*)&kv_s[rr * KVP + j * 8] =
            *(const uint4*)&kb[(size_t)(gh * Wdim + gw) * Cdim + hd * HD + j * 8];
    }
    __syncthreads();

    float qf[32];
    {
        const float4* qp = (const float4*)&qbuf[(size_t)(h * Wdim + w) * Cdim + hd * HD];
        #pragma unroll
        for (int j = 0; j < 8; j++) {
            float4 t = qp[j];
            qf[j * 4] = t.x; qf[j * 4 + 1] = t.y; qf[j * 4 + 2] = t.z; qf[j * 4 + 3] = t.w;
        }
    }

    const int sh = min(max(h - 3, 0), Hdim - KW);
    const int sw = min(max(w - 3, 0), Wdim - KW);
    const int lr0 = sh - o_h, lc0 = sw - o_w;
    const int rh0 = sh - h + 6, rw0 = sw - w + 6;

    float p[KK];
    #pragma unroll
    for (int a = 0; a < KW; a++) {
        #pragma unroll
        for (int c = 0; c < KW; c++) {
            const uint4* kp = (const uint4*)&kv_s[((lr0 + a) * NBW + lc0 + c) * KVP];
            float d = 0.0f;
            #pragma unroll
            for (int j = 0; j < 4; j++) {
                uint4 t = kp[j];
                float2 f;
                f = __bfloat1622float2(*(__nv_bfloat162*)&t.x);
                d = fmaf(qf[j*8+0], f.x, d); d = fmaf(qf[j*8+1], f.y, d);
                f = __bfloat1622float2(*(__nv_bfloat162*)&t.y);
                d = fmaf(qf[j*8+2], f.x, d); d = fmaf(qf[j*8+3], f.y, d);
                f = __bfloat1622float2(*(__nv_bfloat162*)&t.z);
                d = fmaf(qf[j*8+4], f.x, d); d = fmaf(qf[j*8+5], f.y, d);
                f = __bfloat1622float2(*(__nv_bfloat162*)&t.w);
                d = fmaf(qf[j*8+6], f.x, d); d = fmaf(qf[j*8+7], f.y, d);
            }
            p[a * KW + c] = d + rpb_s[(rh0 + a) * RPBW + rw0 + c];
        }
    }

    float mx = -1e30f;
    #pragma unroll
    for (int n = 0; n < KK; n++) mx = fmaxf(mx, p[n]);
    float ssum = 0.0f;
    #pragma unroll
    for (int n = 0; n < KK; n++) { p[n] = __expf(p[n] - mx); ssum += p[n]; }
    const float inv = __fdividef(1.0f, ssum);
    __syncthreads();

    for (int idx = tid; idx < NBR * 4; idx += 128) {
        const int rr = idx >> 2, j = idx & 3;
        const int gh = o_h + rr / NBW, gw = o_w + rr % NBW;
        *(uint4*)&kv_s[rr * KVP + j * 8] =
            *(const uint4*)&vb[(size_t)(gh * Wdim + gw) * Cdim + hd * HD + j * 8];
    }
    __syncthreads();

    float acc[32];
    #pragma unroll
    for (int j = 0; j < 32; j++) acc[j] = 0.0f;
    #pragma unroll
    for (int a = 0; a < KW; a++) {
        #pragma unroll
        for (int c = 0; c < KW; c++) {
            const float pr = p[a * KW + c] * inv;
            const uint4* vp = (const uint4*)&kv_s[((lr0 + a) * NBW + lc0 + c) * KVP];
            #pragma unroll
            for (int j = 0; j < 4; j++) {
                uint4 t = vp[j];
                float2 f;
                f = __bfloat1622float2(*(__nv_bfloat162*)&t.x);
                acc[j*8+0] = fmaf(pr, f.x, acc[j*8+0]); acc[j*8+1] = fmaf(pr, f.y, acc[j*8+1]);
                f = __bfloat1622float2(*(__nv_bfloat162*)&t.y);
                acc[j*8+2] = fmaf(pr, f.x, acc[j*8+2]); acc[j*8+3] = fmaf(pr, f.y, acc[j*8+3]);
                f = __bfloat1622float2(*(__nv_bfloat162*)&t.z);
                acc[j*8+4] = fmaf(pr, f.x, acc[j*8+4]); acc[j*8+5] = fmaf(pr, f.y, acc[j*8+5]);
                f = __bfloat1622float2(*(__nv_bfloat162*)&t.w);
                acc[j*8+6] = fmaf(pr, f.x, acc[j*8+6]); acc[j*8+7] = fmaf(pr, f.y, acc[j*8+7]);
            }
        }
    }
    const size_t base = (size_t)(h * Wdim + w) * Cdim + hd * HD;
    #pragma unroll
    for (int j = 0; j < 16; j++) {
        __nv_bfloat16 h0, l0, h1, l1;
        splitf(acc[j * 2],     h0, l0);
        splitf(acc[j * 2 + 1], h1, l1);
        *(uint32_t*)&oh[base + j * 2] = ((uint32_t)*(uint16_t*)&h1 << 16) | *(uint16_t*)&h0;
        *(uint32_t*)&ol[base + j * 2] = ((uint32_t)*(uint16_t*)&l1 << 16) | *(uint16_t*)&l0;
    }
}

// ---------------- launch -----------------
extern "C" void kernel_launch(void* const* d_in, const int* in_sizes, int n_in,
                              void* d_out, int out_size)
{
    const float* x      = (const float*)d_in[0];
    const float* y      = (const float*)d_in[1];
    const float* qv_w   = (const float*)d_in[2];
    const float* qv_b   = (const float*)d_in[3];
    const float* k_w    = (const float*)d_in[4];
    const float* k_b    = (const float*)d_in[5];
    const float* rpb    = (const float*)d_in[6];
    const float* proj_w = (const float*)d_in[7];
    const float* proj_b = (const float*)d_in[8];
    const float* n1_w   = (const float*)d_in[9];
    const float* n1_b   = (const float*)d_in[10];
    const float* n2_w   = (const float*)d_in[11];
    const float* n2_b   = (const float*)d_in[12];
    const float* fc1_w  = (const float*)d_in[13];
    const float* fc1_b  = (const float*)d_in[14];
    const float* fc2_w  = (const float*)d_in[15];
    const float* fc2_b  = (const float*)d_in[16];
    float* out = (float*)d_out;

    float *p_q, *p_x2;
    __nv_bfloat16 *p_vb, *p_kb, *xnh, *xnl, *yh, *yl, *ath, *atl, *hh, *hl, *wh, *wl;
    cudaGetSymbolAddress((void**)&p_q,  g_q);
    cudaGetSymbolAddress((void**)&p_x2, g_x2);
    cudaGetSymbolAddress((void**)&p_vb, g_vb);
    cudaGetSymbolAddress((void**)&p_kb, g_kb);
    cudaGetSymbolAddress((void**)&xnh, s_xn_hi);
    cudaGetSymbolAddress((void**)&xnl, s_xn_lo);
    cudaGetSymbolAddress((void**)&yh,  s_y_hi);
    cudaGetSymbolAddress((void**)&yl,  s_y_lo);
    cudaGetSymbolAddress((void**)&ath, s_att_hi);
    cudaGetSymbolAddress((void**)&atl, s_att_lo);
    cudaGetSymbolAddress((void**)&hh,  s_h_hi);
    cudaGetSymbolAddress((void**)&hl,  s_h_lo);
    cudaGetSymbolAddress((void**)&wh,  s_w_hi);
    cudaGetSymbolAddress((void**)&wl,  s_w_lo);

    cudaFuncSetAttribute(gemm_qvk,  cudaFuncAttributeMaxDynamicSharedMemorySize, GSMEM);
    cudaFuncSetAttribute(gemm_proj, cudaFuncAttributeMaxDynamicSharedMemorySize, GSMEM);
    cudaFuncSetAttribute(gemm_gelu, cudaFuncAttributeMaxDynamicSharedMemorySize, GSMEM);
    cudaFuncSetAttribute(gemm_res2, cudaFuncAttributeMaxDynamicSharedMemorySize, GSMEM);

    // 1) prep: LN1(x) + split(y) + split(weights)
    prep_kernel<<<12672, 256>>>(x, n1_w, n1_b, y, qv_w, k_w, proj_w, fc1_w, fc2_w,
                                xnh, xnl, yh, yl, wh, wl);

    // 2) fused qv + k GEMMs
    gemm_qvk<<<dim3(3, NPIX / 64), 256, GSMEM>>>(
        xnh, xnl, yh, yl, wh, wl, qv_b, k_b, p_q, p_vb, p_kb);

    // 3) neighborhood attention
    attn_kernel<<<dim3(Wdim / 16, Hdim / 8, HEADS), 128>>>(p_q, p_vb, p_kb, rpb, ath, atl);

    // 4) proj GEMM + residual
    gemm_proj<<<dim3(1, NPIX / 64), 256, GSMEM>>>(
        ath, atl, wh + 49152, wl + 49152, proj_b, x, p_x2);

    // 5) LN2
    ln_kernel<<<NPIX, 128>>>(p_x2, n2_w, n2_b, xnh, xnl);

    // 6) fc1 + GELU
    gemm_gelu<<<dim3(4, NPIX / 64), 256, GSMEM>>>(
        xnh, xnl, wh + 65536, wl + 65536, fc1_b, hh, hl);

    // 7) fc2 + residual -> out
    gemm_res2<<<dim3(1, NPIX / 64), 256, GSMEM>>>(
        hh, hl, wh + 131072, wl + 131072, fc2_b, p_x2, out);
}